// round 3
// baseline (speedup 1.0000x reference)
#include <cuda_runtime.h>
#include <cuda_bf16.h>
#include <math.h>

#define B_ 1024
#define T_ 250
#define D_ 158
#define H_ 128
#define G_ 512          // 4*H
#define M_ (B_*T_)      // 256000 rows
#define P_ 64
#define O_ 22

// ---------------- scratch (device globals: the sanctioned alloc-free path) ----------------
__device__ float g_xn[(size_t)M_ * D_];   // LN output; later reused as layer-1 h output (M_*128 <= M_*158)
__device__ float g_xg[(size_t)M_ * G_];   // precomputed input gates for current layer
__device__ float g_h0[(size_t)M_ * H_];   // layer-0 h sequence
__device__ float g_Wt0[H_ * G_];          // W_hh0 transposed to [k][g]
__device__ float g_Wt1[H_ * G_];

// ---------------- helpers ----------------
__device__ __forceinline__ float sigm_(float x) {
    return 1.f / (1.f + __expf(-x));
}
__device__ __forceinline__ float tanh_fast(float x) {
    float a = fabsf(x);
    float e = __expf(a + a);          // large a -> inf -> t -> 1 (safe)
    float t = 1.f - 2.f / (e + 1.f);
    return copysignf(t, x);
}

// ---------------- W_hh transpose: W[512][128] -> Wt[128][512] ----------------
__global__ void transpose_whh_kernel(const float* __restrict__ W, float* __restrict__ Wt) {
    int idx = blockIdx.x * blockDim.x + threadIdx.x;   // 65536 total
    int g = idx >> 7;
    int k = idx & 127;
    Wt[k * G_ + g] = W[idx];
}

// ---------------- LayerNorm over last dim (158) ----------------
__global__ void __launch_bounds__(256) ln_kernel(const float* __restrict__ x,
                                                 const float* __restrict__ gamma,
                                                 const float* __restrict__ beta,
                                                 float* __restrict__ xn) {
    int row  = blockIdx.x * 8 + (threadIdx.x >> 5);
    int lane = threadIdx.x & 31;
    const float* xr = x + (size_t)row * D_;
    float v[5];
    float s = 0.f, s2 = 0.f;
#pragma unroll
    for (int i = 0; i < 5; i++) {
        int k = lane + 32 * i;
        v[i] = (k < D_) ? xr[k] : 0.f;
        s += v[i];
        s2 = fmaf(v[i], v[i], s2);
    }
#pragma unroll
    for (int o = 16; o; o >>= 1) {
        s  += __shfl_xor_sync(0xffffffffu, s, o);
        s2 += __shfl_xor_sync(0xffffffffu, s2, o);
    }
    float mu  = s * (1.f / D_);
    float var = s2 * (1.f / D_) - mu * mu;
    float inv = rsqrtf(var + 1e-5f);
    float* xo = xn + (size_t)row * D_;
#pragma unroll
    for (int i = 0; i < 5; i++) {
        int k = lane + 32 * i;
        if (k < D_) xo[k] = (v[i] - mu) * inv * gamma[k] + beta[k];
    }
}

// ---------------- tiled fp32 GEMM: C[M,512] = A[M,K] * W[512,K]^T + bias ----------------
// BM=64, BN=64, BK=16, 256 threads, 4x4 microtile per thread.
template <int K>
__global__ void __launch_bounds__(256) gemm_ih_kernel(const float* __restrict__ A,
                                                      const float* __restrict__ W,
                                                      const float* __restrict__ bias,
                                                      float* __restrict__ C) {
    __shared__ float As[16][64];
    __shared__ float Bs[16][64];
    int tid = threadIdx.x;
    int tx = tid & 15, ty = tid >> 4;
    int m0 = blockIdx.y * 64, n0 = blockIdx.x * 64;
    int lr = tid >> 2;
    int lc = (tid & 3) * 4;
    float acc[4][4] = {};
    const float* Arow = A + (size_t)(m0 + lr) * K;
    const float* Wrow = W + (size_t)(n0 + lr) * K;

    for (int k0 = 0; k0 < K; k0 += 16) {
#pragma unroll
        for (int j = 0; j < 4; j++) {
            int k = k0 + lc + j;
            As[lc + j][lr] = (k < K) ? Arow[k] : 0.f;
            Bs[lc + j][lr] = (k < K) ? Wrow[k] : 0.f;
        }
        __syncthreads();
#pragma unroll
        for (int kk = 0; kk < 16; kk++) {
            float4 a4 = *(const float4*)&As[kk][ty * 4];
            float4 b4 = *(const float4*)&Bs[kk][tx * 4];
            float av[4] = {a4.x, a4.y, a4.z, a4.w};
            float bv[4] = {b4.x, b4.y, b4.z, b4.w};
#pragma unroll
            for (int i = 0; i < 4; i++)
#pragma unroll
                for (int j = 0; j < 4; j++)
                    acc[i][j] = fmaf(av[i], bv[j], acc[i][j]);
        }
        __syncthreads();
    }
#pragma unroll
    for (int i = 0; i < 4; i++) {
        size_t m = (size_t)(m0 + ty * 4 + i);
#pragma unroll
        for (int j = 0; j < 4; j++) {
            int n = n0 + tx * 4 + j;
            C[m * G_ + n] = acc[i][j] + bias[n];
        }
    }
}

// ---------------- LSTM recurrence: one CTA owns 4 batch rows for all 250 steps ----------------
// xg: [B*T, 512] (row = b*T + t), Wt: [128][512] k-major, hout: [B*T, 128]
__global__ void __launch_bounds__(256) lstm_layer_kernel(const float* __restrict__ xg,
                                                         const float* __restrict__ Wt,
                                                         float* __restrict__ hout) {
    __shared__ float hs[4][128];
    __shared__ float gs[4][512];
    int tid = threadIdx.x;
    int p  = tid >> 7;        // row pair: rows {2p, 2p+1}
    int gq = tid & 127;       // gate quad: gates [4gq .. 4gq+3]
    int b0 = blockIdx.x * 4;

    for (int i = tid; i < 512; i += 256) (&hs[0][0])[i] = 0.f;
    float c0 = 0.f, c1 = 0.f;
    int r = tid >> 6;         // phase-B row (units 2tid, 2tid+1 share this row)
    int j = (tid & 63) * 2;   // phase-B first hidden index (even)
    __syncthreads();

    const float4* Wt4 = (const float4*)Wt;   // [128][128] float4
    const float* xg_a = xg + (size_t)(b0 + 2 * p) * T_ * G_ + 4 * gq;
    const float* xg_b = xg + (size_t)(b0 + 2 * p + 1) * T_ * G_ + 4 * gq;
    float* hout_base = hout + (size_t)(b0 + r) * T_ * H_ + j;

    for (int t = 0; t < T_; t++) {
        float4 acc0 = *(const float4*)(xg_a + (size_t)t * G_);
        float4 acc1 = *(const float4*)(xg_b + (size_t)t * G_);
        const float* h0p = hs[2 * p];
        const float* h1p = hs[2 * p + 1];
#pragma unroll 4
        for (int k = 0; k < H_; k++) {
            float4 w = Wt4[k * 128 + gq];
            float ha = h0p[k], hb = h1p[k];
            acc0.x = fmaf(w.x, ha, acc0.x);
            acc0.y = fmaf(w.y, ha, acc0.y);
            acc0.z = fmaf(w.z, ha, acc0.z);
            acc0.w = fmaf(w.w, ha, acc0.w);
            acc1.x = fmaf(w.x, hb, acc1.x);
            acc1.y = fmaf(w.y, hb, acc1.y);
            acc1.z = fmaf(w.z, hb, acc1.z);
            acc1.w = fmaf(w.w, hb, acc1.w);
        }
        *(float4*)&gs[2 * p][4 * gq]     = acc0;
        *(float4*)&gs[2 * p + 1][4 * gq] = acc1;
        __syncthreads();

        // gate order i, f, g, o (PyTorch stacking)
        float2 gi = *(float2*)&gs[r][j];
        float2 gf = *(float2*)&gs[r][128 + j];
        float2 gg = *(float2*)&gs[r][256 + j];
        float2 go = *(float2*)&gs[r][384 + j];
        c0 = sigm_(gf.x) * c0 + sigm_(gi.x) * tanh_fast(gg.x);
        c1 = sigm_(gf.y) * c1 + sigm_(gi.y) * tanh_fast(gg.y);
        float h0v = sigm_(go.x) * tanh_fast(c0);
        float h1v = sigm_(go.y) * tanh_fast(c1);
        hs[r][j]     = h0v;
        hs[r][j + 1] = h1v;
        *(float2*)(hout_base + (size_t)t * H_) = make_float2(h0v, h1v);
        __syncthreads();
    }
}

// ---------------- projection head: ReLU(h @ Wp1^T + bp1) @ Wp2^T + bp2 ----------------
__global__ void __launch_bounds__(256) proj_kernel(const float* __restrict__ h,
                                                   const float* __restrict__ Wp1,
                                                   const float* __restrict__ bp1,
                                                   const float* __restrict__ Wp2,
                                                   const float* __restrict__ bp2,
                                                   float* __restrict__ out) {
    __shared__ float w1t[128][65];   // w1t[k][j] = Wp1[j][k] (padded: conflict-free STS/LDS)
    __shared__ float w2t[64][22];    // w2t[k][o] = Wp2[o][k]
    __shared__ float ps[32][64];
    __shared__ float b1s[64];
    __shared__ float b2s[22];
    int tid = threadIdx.x;

    for (int i = tid; i < P_ * H_; i += 256) { int jj = i >> 7, kk = i & 127; w1t[kk][jj] = Wp1[i]; }
    for (int i = tid; i < O_ * P_; i += 256) { int oo = i >> 6, kk = i & 63;  w2t[kk][oo] = Wp2[i]; }
    if (tid < P_) b1s[tid] = bp1[tid];
    if (tid < O_) b2s[tid] = bp2[tid];
    __syncthreads();

    size_t row0 = (size_t)blockIdx.x * 32;
    int jj = tid & 63;
    int rs = tid >> 6;   // uniform within a warp
    float acc[8] = {};
    const float* hrow[8];
#pragma unroll
    for (int rr = 0; rr < 8; rr++) hrow[rr] = h + (row0 + (size_t)rs * 8 + rr) * H_;

    for (int k4 = 0; k4 < 32; k4++) {
        float4 hv[8];
#pragma unroll
        for (int rr = 0; rr < 8; rr++) hv[rr] = *(const float4*)(hrow[rr] + 4 * k4);
#pragma unroll
        for (int kk = 0; kk < 4; kk++) {
            float w = w1t[4 * k4 + kk][jj];
#pragma unroll
            for (int rr = 0; rr < 8; rr++) {
                float hvv = (&hv[rr].x)[kk];
                acc[rr] = fmaf(hvv, w, acc[rr]);
            }
        }
    }
#pragma unroll
    for (int rr = 0; rr < 8; rr++) {
        float v = acc[rr] + b1s[jj];
        ps[rs * 8 + rr][jj] = v > 0.f ? v : 0.f;
    }
    __syncthreads();

    for (int idx = tid; idx < 32 * O_; idx += 256) {
        int rr = idx / O_;
        int oo = idx - rr * O_;
        float s = b2s[oo];
#pragma unroll
        for (int k = 0; k < P_; k++) s = fmaf(ps[rr][k], w2t[k][oo], s);
        out[(row0 + rr) * O_ + oo] = s;
    }
}

// ---------------- launch ----------------
extern "C" void kernel_launch(void* const* d_in, const int* in_sizes, int n_in,
                              void* d_out, int out_size) {
    const float* x     = (const float*)d_in[0];
    const float* ln_g  = (const float*)d_in[1];
    const float* ln_b  = (const float*)d_in[2];
    const float* W_ih0 = (const float*)d_in[3];
    const float* W_hh0 = (const float*)d_in[4];
    const float* b0    = (const float*)d_in[5];
    const float* W_ih1 = (const float*)d_in[6];
    const float* W_hh1 = (const float*)d_in[7];
    const float* b1    = (const float*)d_in[8];
    const float* Wp1   = (const float*)d_in[9];
    const float* bp1   = (const float*)d_in[10];
    const float* Wp2   = (const float*)d_in[11];
    const float* bp2   = (const float*)d_in[12];
    float* out = (float*)d_out;

    float *xn, *xg, *h0, *wt0, *wt1;
    cudaGetSymbolAddress((void**)&xn,  g_xn);
    cudaGetSymbolAddress((void**)&xg,  g_xg);
    cudaGetSymbolAddress((void**)&h0,  g_h0);
    cudaGetSymbolAddress((void**)&wt0, g_Wt0);
    cudaGetSymbolAddress((void**)&wt1, g_Wt1);
    float* h1 = xn;   // reuse LN buffer for layer-1 h output (xn dead after GEMM0)

    transpose_whh_kernel<<<256, 256>>>(W_hh0, wt0);
    transpose_whh_kernel<<<256, 256>>>(W_hh1, wt1);

    ln_kernel<<<M_ / 8, 256>>>(x, ln_g, ln_b, xn);

    gemm_ih_kernel<D_><<<dim3(8, M_ / 64), 256>>>(xn, W_ih0, b0, xg);
    lstm_layer_kernel<<<B_ / 4, 256>>>(xg, wt0, h0);

    gemm_ih_kernel<H_><<<dim3(8, M_ / 64), 256>>>(h0, W_ih1, b1, xg);
    lstm_layer_kernel<<<B_ / 4, 256>>>(xg, wt1, h1);

    proj_kernel<<<M_ / 32, 256>>>(h1, Wp1, bp1, Wp2, bp2, out);
}